// round 1
// baseline (speedup 1.0000x reference)
#include <cuda_runtime.h>
#include <cuda_bf16.h>

// Problem constants
#define Bn 4
#define Cn 64
#define Hn 96
#define Wn 96
#define PLANE (Hn*Wn)            // 9216
#define NPLANES (Bn*Cn)          // 256
#define NTOT (NPLANES*PLANE)     // 2359296
#define CNT_PER_CH (Bn*PLANE)    // 36864
#define BN_EPS 1e-5f

// Scratch (allocation-free rule: __device__ globals)
__device__ float g_y[NTOT];
__device__ float g_sum[Cn];
__device__ float g_sumsq[Cn];

// ---------------------------------------------------------------------------
// Kernel 0: zero the reduction accumulators
// ---------------------------------------------------------------------------
__global__ void zero_kernel() {
    int t = threadIdx.x;
    if (t < Cn) { g_sum[t] = 0.f; g_sumsq[t] = 0.f; }
}

// transform: silu(x) and packed spline coordinate mu = m + u
__device__ __forceinline__ float2 kan_transform(float x) {
    float s = x / (1.0f + __expf(-x));          // silu
    float mu = (x + 2.2f) * 2.5f;               // (x - t0)/h, t0=-2.2, h=0.4
    if (!(mu >= 0.0f && mu < 11.0f)) mu = 11.0f; // sentinel row -> zero coeffs
    return make_float2(s, mu);
}

// ---------------------------------------------------------------------------
// Kernel 1: fused KAN depthwise conv + per-channel sum/sumsq reduction
// grid = (3, 3, 256 planes), block = 256 threads (32x8), 4 output rows/thread
// ---------------------------------------------------------------------------
__global__ __launch_bounds__(256)
void kan_conv_kernel(const float* __restrict__ x,
                     const float* __restrict__ base_weight,    // (9)
                     const float* __restrict__ spline_weight,  // (9,8)
                     const float* __restrict__ spline_scaler)  // (9)
{
    __shared__ float2 s_t[34 * 35];      // (silu, mu) tile with halo, pitch 35
    __shared__ float4 s_coef[12 * 9];    // cubic coeffs per (interval m, tap k)
    __shared__ float  s_bw[9];
    __shared__ float  s_rs[8], s_rq[8];

    const int tid   = threadIdx.x;
    const int plane = blockIdx.z;
    const int ty0   = blockIdx.y * 32;
    const int tx0   = blockIdx.x * 32;

    // ---- build coefficient table (uniform cubic B-spline expansion) ----
    // For x in [t_m, t_{m+1}), u=(x-t_m)/h, nonzero cubic bases are
    // N_{m-3..m}. Row r of F gives poly coeffs (in u) of N_{m-3+r}, x6.
    if (tid < 108) {
        const int m = tid / 9, k = tid % 9;
        float c0 = 0.f, c1 = 0.f, c2 = 0.f, c3 = 0.f;
        if (m < 11) {
            const float F[4][4] = {
                {1.f, -3.f,  3.f, -1.f},   // N_{m-3}
                {4.f,  0.f, -6.f,  3.f},   // N_{m-2}
                {1.f,  3.f,  3.f, -3.f},   // N_{m-1}
                {0.f,  0.f,  0.f,  1.f}    // N_{m}
            };
            const float sc = spline_scaler[k];
            #pragma unroll
            for (int r = 0; r < 4; r++) {
                int j = m - 3 + r;
                if (j >= 0 && j < 8) {
                    float w = spline_weight[k * 8 + j] * sc;
                    c0 += w * F[r][0]; c1 += w * F[r][1];
                    c2 += w * F[r][2]; c3 += w * F[r][3];
                }
            }
        }
        const float inv6 = 1.0f / 6.0f;
        s_coef[m * 9 + k] = make_float4(c0 * inv6, c1 * inv6, c2 * inv6, c3 * inv6);
    }
    if (tid < 9) s_bw[tid] = base_weight[tid];

    // ---- load + transform halo tile (34x34), zero-padded outside plane ----
    const float* xp = x + plane * PLANE;
    for (int i = tid; i < 34 * 34; i += 256) {
        int hy = i / 34, hx = i % 34;
        int gy = ty0 + hy - 1, gx = tx0 + hx - 1;
        float v = (gy >= 0 && gy < Hn && gx >= 0 && gx < Wn) ? xp[gy * Wn + gx] : 0.0f;
        s_t[hy * 35 + hx] = kan_transform(v);
    }
    __syncthreads();

    // ---- compute 32x32 outputs ----
    const int tx  = tid & 31;
    const int tyb = tid >> 5;
    float lsum = 0.f, lsq = 0.f;

    #pragma unroll
    for (int r = 0; r < 4; r++) {
        const int oy = tyb + r * 8;
        float acc = 0.f;
        #pragma unroll
        for (int dy = 0; dy < 3; dy++) {
            #pragma unroll
            for (int dx = 0; dx < 3; dx++) {
                const int k = dy * 3 + dx;
                float2 t = s_t[(oy + dy) * 35 + (tx + dx)];
                int   m = (int)t.y;
                float u = t.y - (float)m;
                float4 cf = s_coef[m * 9 + k];
                float poly = fmaf(u, fmaf(u, fmaf(u, cf.w, cf.z), cf.y), cf.x);
                acc += poly + s_bw[k] * t.x;
            }
        }
        g_y[plane * PLANE + (ty0 + oy) * Wn + (tx0 + tx)] = acc;
        lsum += acc;
        lsq  = fmaf(acc, acc, lsq);
    }

    // ---- block reduction for BN statistics ----
    #pragma unroll
    for (int o = 16; o > 0; o >>= 1) {
        lsum += __shfl_down_sync(0xffffffffu, lsum, o);
        lsq  += __shfl_down_sync(0xffffffffu, lsq,  o);
    }
    if (tx == 0) { s_rs[tyb] = lsum; s_rq[tyb] = lsq; }
    __syncthreads();
    if (tid == 0) {
        float s = 0.f, q = 0.f;
        #pragma unroll
        for (int i = 0; i < 8; i++) { s += s_rs[i]; q += s_rq[i]; }
        const int c = plane & (Cn - 1);
        atomicAdd(&g_sum[c], s);
        atomicAdd(&g_sumsq[c], q);
    }
}

// ---------------------------------------------------------------------------
// Kernel 2: BatchNorm (batch stats) + ReLU, float4 vectorized
// ---------------------------------------------------------------------------
__global__ __launch_bounds__(256)
void bn_relu_kernel(const float* __restrict__ gamma,
                    const float* __restrict__ beta,
                    float* __restrict__ out)
{
    const int i = blockIdx.x * blockDim.x + threadIdx.x;   // float4 index
    if (i >= NTOT / 4) return;
    const int c = ((i * 4) / PLANE) & (Cn - 1);            // PLANE % 4 == 0

    const float invN = 1.0f / (float)CNT_PER_CH;
    float mean = g_sum[c] * invN;
    float var  = g_sumsq[c] * invN - mean * mean;
    float scl  = rsqrtf(var + BN_EPS) * gamma[c];
    float sh   = fmaf(-mean, scl, beta[c]);

    float4 v = reinterpret_cast<const float4*>(g_y)[i];
    float4 o;
    o.x = fmaxf(fmaf(v.x, scl, sh), 0.0f);
    o.y = fmaxf(fmaf(v.y, scl, sh), 0.0f);
    o.z = fmaxf(fmaf(v.z, scl, sh), 0.0f);
    o.w = fmaxf(fmaf(v.w, scl, sh), 0.0f);
    reinterpret_cast<float4*>(out)[i] = o;
}

// ---------------------------------------------------------------------------
extern "C" void kernel_launch(void* const* d_in, const int* in_sizes, int n_in,
                              void* d_out, int out_size)
{
    const float* x             = (const float*)d_in[0];
    const float* base_weight   = (const float*)d_in[1];
    const float* spline_weight = (const float*)d_in[2];
    const float* spline_scaler = (const float*)d_in[3];
    const float* bn_gamma      = (const float*)d_in[4];
    const float* bn_beta       = (const float*)d_in[5];
    float* out                 = (float*)d_out;

    zero_kernel<<<1, 64>>>();

    dim3 grid(3, 3, NPLANES);
    kan_conv_kernel<<<grid, 256>>>(x, base_weight, spline_weight, spline_scaler);

    int nv = NTOT / 4;
    bn_relu_kernel<<<(nv + 255) / 256, 256>>>(bn_gamma, bn_beta, out);
}